// round 1
// baseline (speedup 1.0000x reference)
#include <cuda_runtime.h>
#include <math.h>

#define RTOT 65536
#define CD   768
#define EPS  1e-5f

// Scratch (static device arrays: allocation-free per harness rules)
__device__ float g_xnw[RTOT*CD];   // LN1 output in windowed row order
__device__ float g_qin[RTOT*CD];   // green + blue
__device__ float g_kin[RTOT*CD];   // red
__device__ float g_q[RTOT*CD];
__device__ float g_k[RTOT*CD];
__device__ float g_v[RTOT*CD];
__device__ float g_att[RTOT*CD];
__device__ float g_a[RTOT*CD];     // proj output

// ---------------------------------------------------------------------------
// Kernel 1: LN1 fused with window partition. One block per windowed row.
// ---------------------------------------------------------------------------
__global__ void k_ln1(const float* __restrict__ x,
                      const float* __restrict__ g,
                      const float* __restrict__ b) {
    int wr  = blockIdx.x;
    int win = wr >> 6, t = wr & 63;
    int bb  = win >> 8, rem = win & 255;
    int wh  = rem >> 4, ww = rem & 15;
    int ii  = t >> 3,  jj = t & 7;
    int sr  = bb * 16384 + (wh * 8 + ii) * 128 + ww * 8 + jj;  // spatial row

    const float* xr = x + (size_t)sr * CD;
    int tid = threadIdx.x;
    float v0 = xr[tid], v1 = xr[tid + 256], v2 = xr[tid + 512];
    float ls = v0 + v1 + v2;
    float lq = v0*v0 + v1*v1 + v2*v2;
    #pragma unroll
    for (int o = 16; o > 0; o >>= 1) {
        ls += __shfl_xor_sync(0xffffffffu, ls, o);
        lq += __shfl_xor_sync(0xffffffffu, lq, o);
    }
    __shared__ float ss[8], sq[8];
    int wid = tid >> 5;
    if ((tid & 31) == 0) { ss[wid] = ls; sq[wid] = lq; }
    __syncthreads();
    float S = 0.f, Q = 0.f;
    #pragma unroll
    for (int k = 0; k < 8; k++) { S += ss[k]; Q += sq[k]; }
    float m   = S * (1.f / 768.f);
    float var = Q * (1.f / 768.f) - m * m;
    float inv = rsqrtf(var + EPS);

    float* o = g_xnw + (size_t)wr * CD;
    o[tid      ] = (v0 - m) * inv * g[tid      ] + b[tid      ];
    o[tid + 256] = (v1 - m) * inv * g[tid + 256] + b[tid + 256];
    o[tid + 512] = (v2 - m) * inv * g[tid + 512] + b[tid + 512];
}

// ---------------------------------------------------------------------------
// Kernel 2: the reshape(3,..)/tile shuffle.
//   red[r,c]   = xnw[(0*R+rho)//3, ((0*R+rho)%3)*256 + c%256]
//   green/blue = same with s=1 / s=2, rho = (3r + c//256) mod R
// Build kin = red, qin = green + blue.
// ---------------------------------------------------------------------------
__global__ void k_gather() {
    int r   = blockIdx.x;
    int tid = threadIdx.x;  // 256 threads: one 256-channel block per iteration
    #pragma unroll
    for (int cb = 0; cb < 3; cb++) {
        int rho = (3 * r + cb) & 65535;
        int w0 = rho, w1 = 65536 + rho, w2 = 131072 + rho;
        const float* s0 = g_xnw + (size_t)(w0 / 3) * CD + (w0 % 3) * 256;
        const float* s1 = g_xnw + (size_t)(w1 / 3) * CD + (w1 % 3) * 256;
        const float* s2 = g_xnw + (size_t)(w2 / 3) * CD + (w2 % 3) * 256;
        float red = s0[tid];
        float gb  = s1[tid] + s2[tid];
        size_t o = (size_t)r * CD + cb * 256 + tid;
        g_kin[o] = red;
        g_qin[o] = gb;
    }
}

// ---------------------------------------------------------------------------
// Kernel 3: fp32 SGEMM  C[r,n] = sum_k A[r,k] * W[n*768+k] (+ bias[n])
// A: (65536 x 768) row-major from a selected scratch buffer, W row-major.
// 128x128 tile, BK=8, 256 threads, 8x8 per-thread microtile.
// ---------------------------------------------------------------------------
__device__ __forceinline__ const float* srcSel(int s) {
    switch (s) { case 0: return g_qin; case 1: return g_kin; default: return g_att; }
}
__device__ __forceinline__ float* dstSel(int s) {
    switch (s) { case 0: return g_q; case 1: return g_k; case 2: return g_v; default: return g_a; }
}

__global__ __launch_bounds__(256) void k_sgemm(int aSel, int cSel,
                                               const float* __restrict__ W,
                                               const float* __restrict__ bias) {
    const float* A = srcSel(aSel);
    float* C = dstSel(cSel);
    __shared__ float As[8][128];
    __shared__ float Bs[8][128];

    int tid = threadIdx.x;
    int m0 = blockIdx.y * 128, n0 = blockIdx.x * 128;
    int lm = tid >> 1;            // 0..127
    int lk = (tid & 1) * 4;       // 0 or 4
    const float* Ap = A + (size_t)(m0 + lm) * CD + lk;
    const float* Wp = W + (size_t)(n0 + lm) * CD + lk;

    float acc[8][8];
    #pragma unroll
    for (int i = 0; i < 8; i++)
        #pragma unroll
        for (int j = 0; j < 8; j++) acc[i][j] = 0.f;

    int tm = (tid >> 4) * 8;
    int tn = (tid & 15) * 8;

    for (int k0 = 0; k0 < CD; k0 += 8) {
        float4 av = *(const float4*)(Ap + k0);
        float4 wv = *(const float4*)(Wp + k0);
        As[lk + 0][lm] = av.x; As[lk + 1][lm] = av.y;
        As[lk + 2][lm] = av.z; As[lk + 3][lm] = av.w;
        Bs[lk + 0][lm] = wv.x; Bs[lk + 1][lm] = wv.y;
        Bs[lk + 2][lm] = wv.z; Bs[lk + 3][lm] = wv.w;
        __syncthreads();
        #pragma unroll
        for (int kk = 0; kk < 8; kk++) {
            float4 a0 = *(const float4*)&As[kk][tm];
            float4 a1 = *(const float4*)&As[kk][tm + 4];
            float4 b0 = *(const float4*)&Bs[kk][tn];
            float4 b1 = *(const float4*)&Bs[kk][tn + 4];
            float ar[8] = {a0.x, a0.y, a0.z, a0.w, a1.x, a1.y, a1.z, a1.w};
            float br[8] = {b0.x, b0.y, b0.z, b0.w, b1.x, b1.y, b1.z, b1.w};
            #pragma unroll
            for (int i = 0; i < 8; i++)
                #pragma unroll
                for (int j = 0; j < 8; j++)
                    acc[i][j] += ar[i] * br[j];
        }
        __syncthreads();
    }

    #pragma unroll
    for (int i = 0; i < 8; i++) {
        float* Crow = C + (size_t)(m0 + tm + i) * CD + n0 + tn;
        float4 v0 = make_float4(acc[i][0], acc[i][1], acc[i][2], acc[i][3]);
        float4 v1 = make_float4(acc[i][4], acc[i][5], acc[i][6], acc[i][7]);
        if (bias) {
            const float* bp = bias + n0 + tn;
            v0.x += bp[0]; v0.y += bp[1]; v0.z += bp[2]; v0.w += bp[3];
            v1.x += bp[4]; v1.y += bp[5]; v1.z += bp[6]; v1.w += bp[7];
        }
        *(float4*)(Crow)     = v0;
        *(float4*)(Crow + 4) = v1;
    }
}

// ---------------------------------------------------------------------------
// Kernel 4: attention, one block per (window, head). N=64, D=64.
// bufA: Q then V; bufB: K then P. Pitch 65 -> conflict-free row-indexed access.
// Thread (tr,tc) computes a 4x4 microtile of S and later of O.
// Softmax reduction is shfl-only over the 16-lane tc-group.
// ---------------------------------------------------------------------------
__global__ __launch_bounds__(256) void k_attn() {
    __shared__ float bufA[64][65];
    __shared__ float bufB[64][65];
    int wwin = blockIdx.x;
    int hd   = blockIdx.y;
    int r0 = wwin * 64;
    int co = hd * 64;
    int tid = threadIdx.x;

    // cooperative load Q -> bufA, K -> bufB
    {
        int row = tid >> 4;
        int c4  = (tid & 15) * 4;
        #pragma unroll
        for (int p = 0; p < 4; p++) {
            int rr = p * 16 + row;
            size_t gidx = (size_t)(r0 + rr) * CD + co + c4;
            float4 q = *(const float4*)&g_q[gidx];
            float4 k = *(const float4*)&g_k[gidx];
            bufA[rr][c4+0]=q.x; bufA[rr][c4+1]=q.y; bufA[rr][c4+2]=q.z; bufA[rr][c4+3]=q.w;
            bufB[rr][c4+0]=k.x; bufB[rr][c4+1]=k.y; bufB[rr][c4+2]=k.z; bufB[rr][c4+3]=k.w;
        }
    }
    __syncthreads();

    int tr = tid >> 4;   // rows tr*4 .. tr*4+3
    int tc = tid & 15;   // cols tc*4 .. tc*4+3

    float sv[4][4];
    #pragma unroll
    for (int i = 0; i < 4; i++)
        #pragma unroll
        for (int j = 0; j < 4; j++) sv[i][j] = 0.f;

    for (int d = 0; d < 64; d++) {
        float qa[4], kb[4];
        #pragma unroll
        for (int i = 0; i < 4; i++) qa[i] = bufA[tr*4+i][d];
        #pragma unroll
        for (int j = 0; j < 4; j++) kb[j] = bufB[tc*4+j][d];
        #pragma unroll
        for (int i = 0; i < 4; i++)
            #pragma unroll
            for (int j = 0; j < 4; j++)
                sv[i][j] += qa[i] * kb[j];
    }

    const float scale = 0.125f;  // 64^-0.5
    #pragma unroll
    for (int i = 0; i < 4; i++) {
        #pragma unroll
        for (int j = 0; j < 4; j++) sv[i][j] *= scale;
        float m = fmaxf(fmaxf(sv[i][0], sv[i][1]), fmaxf(sv[i][2], sv[i][3]));
        #pragma unroll
        for (int o = 1; o < 16; o <<= 1) m = fmaxf(m, __shfl_xor_sync(0xffffffffu, m, o));
        float s = 0.f;
        #pragma unroll
        for (int j = 0; j < 4; j++) { sv[i][j] = __expf(sv[i][j] - m); s += sv[i][j]; }
        #pragma unroll
        for (int o = 1; o < 16; o <<= 1) s += __shfl_xor_sync(0xffffffffu, s, o);
        float inv = 1.f / s;
        #pragma unroll
        for (int j = 0; j < 4; j++) sv[i][j] *= inv;
    }
    __syncthreads();  // everyone done reading Q (bufA) and K (bufB)

    // store P -> bufB, load V -> bufA
    #pragma unroll
    for (int i = 0; i < 4; i++)
        #pragma unroll
        for (int j = 0; j < 4; j++)
            bufB[tr*4+i][tc*4+j] = sv[i][j];
    {
        int row = tid >> 4;
        int c4  = (tid & 15) * 4;
        #pragma unroll
        for (int p = 0; p < 4; p++) {
            int rr = p * 16 + row;
            size_t gidx = (size_t)(r0 + rr) * CD + co + c4;
            float4 v = *(const float4*)&g_v[gidx];
            bufA[rr][c4+0]=v.x; bufA[rr][c4+1]=v.y; bufA[rr][c4+2]=v.z; bufA[rr][c4+3]=v.w;
        }
    }
    __syncthreads();

    // O = P @ V
    float ov[4][4];
    #pragma unroll
    for (int i = 0; i < 4; i++)
        #pragma unroll
        for (int j = 0; j < 4; j++) ov[i][j] = 0.f;
    for (int j = 0; j < 64; j++) {
        float pa[4], vb[4];
        #pragma unroll
        for (int i = 0; i < 4; i++) pa[i] = bufB[tr*4+i][j];
        #pragma unroll
        for (int u = 0; u < 4; u++) vb[u] = bufA[j][tc*4+u];
        #pragma unroll
        for (int i = 0; i < 4; i++)
            #pragma unroll
            for (int u = 0; u < 4; u++)
                ov[i][u] += pa[i] * vb[u];
    }
    #pragma unroll
    for (int i = 0; i < 4; i++) {
        float4 o4 = make_float4(ov[i][0], ov[i][1], ov[i][2], ov[i][3]);
        *(float4*)&g_att[(size_t)(r0 + tr*4 + i) * CD + co + tc*4] = o4;
    }
}

// ---------------------------------------------------------------------------
// Kernel 5: fused LN2 + MLP. Hidden dim is 1, so:
//   s = (sum(a*g2*f1) - mean(a)*sum(g2*f1)) / sqrt(var(a)+eps) + sum(b2*f1) + f1b
//   out[r,c] = gelu(s) * f2w[c] + f2b[c]     (output rows are windowed order)
// ---------------------------------------------------------------------------
__global__ void k_final(const float* __restrict__ n2g, const float* __restrict__ n2b,
                        const float* __restrict__ f1w, const float* __restrict__ f1b,
                        const float* __restrict__ f2w, const float* __restrict__ f2b,
                        float* __restrict__ out) {
    int r = blockIdx.x;
    const float* a = g_a + (size_t)r * CD;
    int tid = threadIdx.x;
    float s1 = 0.f, s2 = 0.f, s3 = 0.f, s4 = 0.f, s5 = 0.f;
    #pragma unroll
    for (int u = 0; u < 3; u++) {
        int c = tid + 256 * u;
        float x = a[c];
        float wt = n2g[c] * f1w[c];
        s1 += x; s2 += x * x; s3 += x * wt; s4 += wt; s5 += n2b[c] * f1w[c];
    }
    #pragma unroll
    for (int o = 16; o > 0; o >>= 1) {
        s1 += __shfl_xor_sync(0xffffffffu, s1, o);
        s2 += __shfl_xor_sync(0xffffffffu, s2, o);
        s3 += __shfl_xor_sync(0xffffffffu, s3, o);
        s4 += __shfl_xor_sync(0xffffffffu, s4, o);
        s5 += __shfl_xor_sync(0xffffffffu, s5, o);
    }
    __shared__ float sh[8][5];
    int wid = tid >> 5;
    if ((tid & 31) == 0) {
        sh[wid][0]=s1; sh[wid][1]=s2; sh[wid][2]=s3; sh[wid][3]=s4; sh[wid][4]=s5;
    }
    __syncthreads();
    float S1=0.f,S2=0.f,S3=0.f,S4=0.f,S5=0.f;
    #pragma unroll
    for (int k = 0; k < 8; k++) {
        S1+=sh[k][0]; S2+=sh[k][1]; S3+=sh[k][2]; S4+=sh[k][3]; S5+=sh[k][4];
    }
    float m   = S1 * (1.f / 768.f);
    float var = S2 * (1.f / 768.f) - m * m;
    float inv = rsqrtf(var + EPS);
    float s   = (S3 - m * S4) * inv + S5 + f1b[0];
    float hdn = 0.5f * s * (1.f + erff(s * 0.70710678118654752f));

    float* o = out + (size_t)r * CD;
    #pragma unroll
    for (int u = 0; u < 3; u++) {
        int c = tid + 256 * u;
        o[c] = hdn * f2w[c] + f2b[c];
    }
}

// ---------------------------------------------------------------------------
extern "C" void kernel_launch(void* const* d_in, const int* in_sizes, int n_in,
                              void* d_out, int out_size) {
    const float* x     = (const float*)d_in[0];
    const float* n1g   = (const float*)d_in[1];
    const float* n1b   = (const float*)d_in[2];
    const float* n2g   = (const float*)d_in[3];
    const float* n2b   = (const float*)d_in[4];
    const float* qkvw  = (const float*)d_in[5];
    const float* projw = (const float*)d_in[6];
    const float* projb = (const float*)d_in[7];
    const float* f1w   = (const float*)d_in[8];
    const float* f1b   = (const float*)d_in[9];
    const float* f2w   = (const float*)d_in[10];
    const float* f2b   = (const float*)d_in[11];
    float* out = (float*)d_out;

    k_ln1<<<RTOT, 256>>>(x, n1g, n1b);
    k_gather<<<RTOT, 256>>>();

    dim3 gg(6, 512);
    k_sgemm<<<gg, 256>>>(0, 0, qkvw,               nullptr);  // Q = qin @ Wq^T
    k_sgemm<<<gg, 256>>>(1, 1, qkvw + 589824,      nullptr);  // K = kin @ Wk^T
    k_sgemm<<<gg, 256>>>(1, 2, qkvw + 2 * 589824,  nullptr);  // V = kin @ Wv^T

    k_attn<<<dim3(1024, 12), 256>>>();

    k_sgemm<<<gg, 256>>>(2, 3, projw, projb);                 // a = att @ Wp^T + b

    k_final<<<RTOT, 256>>>(n2g, n2b, f1w, f1b, f2w, f2b, out);
}

// round 3
// speedup vs baseline: 1.1305x; 1.1305x over previous
#include <cuda_runtime.h>
#include <math.h>

#define RTOT 65536
#define CD   768
#define EPS  1e-5f

// Scratch (static device arrays: allocation-free per harness rules)
__device__ float g_xnw[RTOT*CD];   // LN1 output in windowed row order
__device__ float g_qin[RTOT*CD];   // green + blue
__device__ float g_kin[RTOT*CD];   // red
__device__ float g_q[RTOT*CD];
__device__ float g_k[RTOT*CD];
__device__ float g_v[RTOT*CD];
__device__ float g_att[RTOT*CD];
__device__ float g_a[RTOT*CD];     // proj output

// ---------------------------------------------------------------------------
// Kernel 1: LN1 fused with window partition. One block per windowed row.
// ---------------------------------------------------------------------------
__global__ void k_ln1(const float* __restrict__ x,
                      const float* __restrict__ g,
                      const float* __restrict__ b) {
    int wr  = blockIdx.x;
    int win = wr >> 6, t = wr & 63;
    int bb  = win >> 8, rem = win & 255;
    int wh  = rem >> 4, ww = rem & 15;
    int ii  = t >> 3,  jj = t & 7;
    int sr  = bb * 16384 + (wh * 8 + ii) * 128 + ww * 8 + jj;  // spatial row

    const float* xr = x + (size_t)sr * CD;
    int tid = threadIdx.x;
    float v0 = xr[tid], v1 = xr[tid + 256], v2 = xr[tid + 512];
    float ls = v0 + v1 + v2;
    float lq = v0*v0 + v1*v1 + v2*v2;
    #pragma unroll
    for (int o = 16; o > 0; o >>= 1) {
        ls += __shfl_xor_sync(0xffffffffu, ls, o);
        lq += __shfl_xor_sync(0xffffffffu, lq, o);
    }
    __shared__ float ss[8], sq[8];
    int wid = tid >> 5;
    if ((tid & 31) == 0) { ss[wid] = ls; sq[wid] = lq; }
    __syncthreads();
    float S = 0.f, Q = 0.f;
    #pragma unroll
    for (int k = 0; k < 8; k++) { S += ss[k]; Q += sq[k]; }
    float m   = S * (1.f / 768.f);
    float var = Q * (1.f / 768.f) - m * m;
    float inv = rsqrtf(var + EPS);

    float* o = g_xnw + (size_t)wr * CD;
    o[tid      ] = (v0 - m) * inv * g[tid      ] + b[tid      ];
    o[tid + 256] = (v1 - m) * inv * g[tid + 256] + b[tid + 256];
    o[tid + 512] = (v2 - m) * inv * g[tid + 512] + b[tid + 512];
}

// ---------------------------------------------------------------------------
// Kernel 2: the reshape(3,..)/tile shuffle.
// Build kin = red, qin = green + blue.
// ---------------------------------------------------------------------------
__global__ void k_gather() {
    int r   = blockIdx.x;
    int tid = threadIdx.x;
    #pragma unroll
    for (int cb = 0; cb < 3; cb++) {
        int rho = (3 * r + cb) & 65535;
        int w0 = rho, w1 = 65536 + rho, w2 = 131072 + rho;
        const float* s0 = g_xnw + (size_t)(w0 / 3) * CD + (w0 % 3) * 256;
        const float* s1 = g_xnw + (size_t)(w1 / 3) * CD + (w1 % 3) * 256;
        const float* s2 = g_xnw + (size_t)(w2 / 3) * CD + (w2 % 3) * 256;
        float red = s0[tid];
        float gb  = s1[tid] + s2[tid];
        size_t o = (size_t)r * CD + cb * 256 + tid;
        g_kin[o] = red;
        g_qin[o] = gb;
    }
}

// ---------------------------------------------------------------------------
// Kernel 3: tf32 tensor-core GEMM  C[r,n] = sum_k A[r,k]*W[n,k] (+bias[n])
// 128x128x32 tiles, 256 threads (8 warps 4x2, warp tile 32x64),
// mma.sync.m16n8k8.tf32, cp.async double-buffered, XOR-swizzled smem.
// ---------------------------------------------------------------------------
__device__ __forceinline__ const float* srcSel(int s) {
    switch (s) { case 0: return g_qin; case 1: return g_kin; default: return g_att; }
}
__device__ __forceinline__ float* dstSel(int s) {
    switch (s) { case 0: return g_q; case 1: return g_k; case 2: return g_v; default: return g_a; }
}

__device__ __forceinline__ unsigned f2tf(float f) {
    unsigned u;
    asm("cvt.rna.tf32.f32 %0, %1;" : "=r"(u) : "f"(f));
    return u;
}
__device__ __forceinline__ void cp16(float* dst, const float* src) {
    unsigned d = (unsigned)__cvta_generic_to_shared(dst);
    asm volatile("cp.async.cg.shared.global [%0], [%1], 16;\n" :: "r"(d), "l"(src));
}
// swizzled smem index for a 128x32 fp32 tile (16B granules XOR row)
__device__ __forceinline__ int smidx(int r, int k) {
    return r * 32 + ((((k >> 2) ^ (r & 7))) << 2) + (k & 3);
}

__global__ __launch_bounds__(256, 2) void k_mma(int aSel, int cSel,
                                                const float* __restrict__ W,
                                                const float* __restrict__ bias) {
    extern __shared__ float sm[];
    const float* A = srcSel(aSel);
    float* C = dstSel(cSel);

    int tid  = threadIdx.x;
    int lane = tid & 31, wid = tid >> 5;
    int wm = wid & 3, wn = wid >> 2;          // warp grid 4 (m) x 2 (n)
    int m0 = blockIdx.y * 128, n0 = blockIdx.x * 128;
    int g  = lane >> 2, tg = lane & 3;

    float* AsB[2] = { sm,         sm + 4096 };
    float* BsB[2] = { sm + 8192,  sm + 12288 };

    int lr = tid >> 1;    // 0..127 (tile row)
    int ls = tid & 1;
    const float* Ar = A + (size_t)(m0 + lr) * CD;
    const float* Wr = W + (size_t)(n0 + lr) * CD;

    auto loadTile = [&](int buf, int k0) {
        float* As = AsB[buf]; float* Bs = BsB[buf];
        #pragma unroll
        for (int j = 0; j < 4; j++) {
            int s  = ls + 2 * j;            // 16B segment 0..7
            int sd = s ^ (lr & 7);          // swizzled segment
            cp16(&As[lr * 32 + sd * 4], Ar + k0 + s * 4);
            cp16(&Bs[lr * 32 + sd * 4], Wr + k0 + s * 4);
        }
    };

    float acc[2][8][4];
    #pragma unroll
    for (int i = 0; i < 2; i++)
        #pragma unroll
        for (int j = 0; j < 8; j++)
            #pragma unroll
            for (int c = 0; c < 4; c++) acc[i][j][c] = 0.f;

    loadTile(0, 0);
    asm volatile("cp.async.commit_group;\n");

    int buf = 0;
    for (int kt = 0; kt < 24; kt++) {
        if (kt < 23) loadTile(buf ^ 1, (kt + 1) * 32);
        asm volatile("cp.async.commit_group;\n");
        asm volatile("cp.async.wait_group 1;\n");
        __syncthreads();

        float* As = AsB[buf]; float* Bs = BsB[buf];
        #pragma unroll
        for (int kk = 0; kk < 4; kk++) {
            int kb = kk * 8 + tg;
            unsigned a[2][4];
            #pragma unroll
            for (int im = 0; im < 2; im++) {
                int r0 = wm * 32 + im * 16 + g;
                a[im][0] = f2tf(As[smidx(r0,     kb    )]);
                a[im][1] = f2tf(As[smidx(r0 + 8, kb    )]);
                a[im][2] = f2tf(As[smidx(r0,     kb + 4)]);
                a[im][3] = f2tf(As[smidx(r0 + 8, kb + 4)]);
            }
            unsigned b[8][2];
            #pragma unroll
            for (int in_ = 0; in_ < 8; in_++) {
                int n = wn * 64 + in_ * 8 + g;
                b[in_][0] = f2tf(Bs[smidx(n, kb    )]);
                b[in_][1] = f2tf(Bs[smidx(n, kb + 4)]);
            }
            #pragma unroll
            for (int im = 0; im < 2; im++)
                #pragma unroll
                for (int in_ = 0; in_ < 8; in_++) {
                    float* c = acc[im][in_];
                    asm volatile(
                        "mma.sync.aligned.m16n8k8.row.col.f32.tf32.tf32.f32 "
                        "{%0,%1,%2,%3}, {%4,%5,%6,%7}, {%8,%9}, {%0,%1,%2,%3};\n"
                        : "+f"(c[0]), "+f"(c[1]), "+f"(c[2]), "+f"(c[3])
                        : "r"(a[im][0]), "r"(a[im][1]), "r"(a[im][2]), "r"(a[im][3]),
                          "r"(b[in_][0]), "r"(b[in_][1]));
                }
        }
        __syncthreads();
        buf ^= 1;
    }

    // Epilogue
    #pragma unroll
    for (int im = 0; im < 2; im++) {
        int row = m0 + wm * 32 + im * 16 + g;
        #pragma unroll
        for (int in_ = 0; in_ < 8; in_++) {
            int col = n0 + wn * 64 + in_ * 8 + 2 * tg;
            float bv0 = 0.f, bv1 = 0.f;
            if (bias) { bv0 = bias[col]; bv1 = bias[col + 1]; }
            float2 v0 = make_float2(acc[im][in_][0] + bv0, acc[im][in_][1] + bv1);
            float2 v1 = make_float2(acc[im][in_][2] + bv0, acc[im][in_][3] + bv1);
            *(float2*)(C + (size_t)row * CD + col)       = v0;
            *(float2*)(C + (size_t)(row + 8) * CD + col) = v1;
        }
    }
}

// ---------------------------------------------------------------------------
// Kernel 4: attention, one block per (window, head). N=64, D=64. (fp32)
// ---------------------------------------------------------------------------
__global__ __launch_bounds__(256) void k_attn() {
    __shared__ float bufA[64][65];
    __shared__ float bufB[64][65];
    int wwin = blockIdx.x;
    int hd   = blockIdx.y;
    int r0 = wwin * 64;
    int co = hd * 64;
    int tid = threadIdx.x;

    {
        int row = tid >> 4;
        int c4  = (tid & 15) * 4;
        #pragma unroll
        for (int p = 0; p < 4; p++) {
            int rr = p * 16 + row;
            size_t gidx = (size_t)(r0 + rr) * CD + co + c4;
            float4 q = *(const float4*)&g_q[gidx];
            float4 k = *(const float4*)&g_k[gidx];
            bufA[rr][c4+0]=q.x; bufA[rr][c4+1]=q.y; bufA[rr][c4+2]=q.z; bufA[rr][c4+3]=q.w;
            bufB[rr][c4+0]=k.x; bufB[rr][c4+1]=k.y; bufB[rr][c4+2]=k.z; bufB[rr][c4+3]=k.w;
        }
    }
    __syncthreads();

    int tr = tid >> 4;
    int tc = tid & 15;

    float sv[4][4];
    #pragma unroll
    for (int i = 0; i < 4; i++)
        #pragma unroll
        for (int j = 0; j < 4; j++) sv[i][j] = 0.f;

    for (int d = 0; d < 64; d++) {
        float qa[4], kb[4];
        #pragma unroll
        for (int i = 0; i < 4; i++) qa[i] = bufA[tr*4+i][d];
        #pragma unroll
        for (int j = 0; j < 4; j++) kb[j] = bufB[tc*4+j][d];
        #pragma unroll
        for (int i = 0; i < 4; i++)
            #pragma unroll
            for (int j = 0; j < 4; j++)
                sv[i][j] += qa[i] * kb[j];
    }

    const float scale = 0.125f;
    #pragma unroll
    for (int i = 0; i < 4; i++) {
        #pragma unroll
        for (int j = 0; j < 4; j++) sv[i][j] *= scale;
        float m = fmaxf(fmaxf(sv[i][0], sv[i][1]), fmaxf(sv[i][2], sv[i][3]));
        #pragma unroll
        for (int o = 1; o < 16; o <<= 1) m = fmaxf(m, __shfl_xor_sync(0xffffffffu, m, o));
        float s = 0.f;
        #pragma unroll
        for (int j = 0; j < 4; j++) { sv[i][j] = __expf(sv[i][j] - m); s += sv[i][j]; }
        #pragma unroll
        for (int o = 1; o < 16; o <<= 1) s += __shfl_xor_sync(0xffffffffu, s, o);
        float inv = 1.f / s;
        #pragma unroll
        for (int j = 0; j < 4; j++) sv[i][j] *= inv;
    }
    __syncthreads();

    #pragma unroll
    for (int i = 0; i < 4; i++)
        #pragma unroll
        for (int j = 0; j < 4; j++)
            bufB[tr*4+i][tc*4+j] = sv[i][j];
    {
        int row = tid >> 4;
        int c4  = (tid & 15) * 4;
        #pragma unroll
        for (int p = 0; p < 4; p++) {
            int rr = p * 16 + row;
            size_t gidx = (size_t)(r0 + rr) * CD + co + c4;
            float4 v = *(const float4*)&g_v[gidx];
            bufA[rr][c4+0]=v.x; bufA[rr][c4+1]=v.y; bufA[rr][c4+2]=v.z; bufA[rr][c4+3]=v.w;
        }
    }
    __syncthreads();

    float ov[4][4];
    #pragma unroll
    for (int i = 0; i < 4; i++)
        #pragma unroll
        for (int j = 0; j < 4; j++) ov[i][j] = 0.f;
    for (int j = 0; j < 64; j++) {
        float pa[4], vb[4];
        #pragma unroll
        for (int i = 0; i < 4; i++) pa[i] = bufB[tr*4+i][j];
        #pragma unroll
        for (int u = 0; u < 4; u++) vb[u] = bufA[j][tc*4+u];
        #pragma unroll
        for (int i = 0; i < 4; i++)
            #pragma unroll
            for (int u = 0; u < 4; u++)
                ov[i][u] += pa[i] * vb[u];
    }
    #pragma unroll
    for (int i = 0; i < 4; i++) {
        float4 o4 = make_float4(ov[i][0], ov[i][1], ov[i][2], ov[i][3]);
        *(float4*)&g_att[(size_t)(r0 + tr*4 + i) * CD + co + tc*4] = o4;
    }
}

// ---------------------------------------------------------------------------
// Kernel 5: fused LN2 + MLP (hidden dim 1 -> rank-1 output).
// ---------------------------------------------------------------------------
__global__ void k_final(const float* __restrict__ n2g, const float* __restrict__ n2b,
                        const float* __restrict__ f1w, const float* __restrict__ f1b,
                        const float* __restrict__ f2w, const float* __restrict__ f2b,
                        float* __restrict__ out) {
    int r = blockIdx.x;
    const float* a = g_a + (size_t)r * CD;
    int tid = threadIdx.x;
    float s1 = 0.f, s2 = 0.f, s3 = 0.f, s4 = 0.f, s5 = 0.f;
    #pragma unroll
    for (int u = 0; u < 3; u++) {
        int c = tid + 256 * u;
        float x = a[c];
        float wt = n2g[c] * f1w[c];
        s1 += x; s2 += x * x; s3 += x * wt; s4 += wt; s5 += n2b[c] * f1w[c];
    }
    #pragma unroll
    for (int o = 16; o > 0; o >>= 1) {
        s1 += __shfl_xor_sync(0xffffffffu, s1, o);
        s2 += __shfl_xor_sync(0xffffffffu, s2, o);
        s3 += __shfl_xor_sync(0xffffffffu, s3, o);
        s4 += __shfl_xor_sync(0xffffffffu, s4, o);
        s5 += __shfl_xor_sync(0xffffffffu, s5, o);
    }
    __shared__ float sh[8][5];
    int wid = tid >> 5;
    if ((tid & 31) == 0) {
        sh[wid][0]=s1; sh[wid][1]=s2; sh[wid][2]=s3; sh[wid][3]=s4; sh[wid][4]=s5;
    }
    __syncthreads();
    float S1=0.f,S2=0.f,S3=0.f,S4=0.f,S5=0.f;
    #pragma unroll
    for (int k = 0; k < 8; k++) {
        S1+=sh[k][0]; S2+=sh[k][1]; S3+=sh[k][2]; S4+=sh[k][3]; S5+=sh[k][4];
    }
    float m   = S1 * (1.f / 768.f);
    float var = S2 * (1.f / 768.f) - m * m;
    float inv = rsqrtf(var + EPS);
    float s   = (S3 - m * S4) * inv + S5 + f1b[0];
    float hdn = 0.5f * s * (1.f + erff(s * 0.70710678118654752f));

    float* o = out + (size_t)r * CD;
    #pragma unroll
    for (int u = 0; u < 3; u++) {
        int c = tid + 256 * u;
        o[c] = hdn * f2w[c] + f2b[c];
    }
}

// ---------------------------------------------------------------------------
extern "C" void kernel_launch(void* const* d_in, const int* in_sizes, int n_in,
                              void* d_out, int out_size) {
    const float* x     = (const float*)d_in[0];
    const float* n1g   = (const float*)d_in[1];
    const float* n1b   = (const float*)d_in[2];
    const float* n2g   = (const float*)d_in[3];
    const float* n2b   = (const float*)d_in[4];
    const float* qkvw  = (const float*)d_in[5];
    const float* projw = (const float*)d_in[6];
    const float* projb = (const float*)d_in[7];
    const float* f1w   = (const float*)d_in[8];
    const float* f1b   = (const float*)d_in[9];
    const float* f2w   = (const float*)d_in[10];
    const float* f2b   = (const float*)d_in[11];
    float* out = (float*)d_out;

    cudaFuncSetAttribute(k_mma, cudaFuncAttributeMaxDynamicSharedMemorySize, 65536);

    k_ln1<<<RTOT, 256>>>(x, n1g, n1b);
    k_gather<<<RTOT, 256>>>();

    dim3 gg(6, 512);
    k_mma<<<gg, 256, 65536>>>(0, 0, qkvw,              nullptr);  // Q = qin @ Wq^T
    k_mma<<<gg, 256, 65536>>>(1, 1, qkvw + 589824,     nullptr);  // K = kin @ Wk^T
    k_mma<<<gg, 256, 65536>>>(1, 2, qkvw + 2 * 589824, nullptr);  // V = kin @ Wv^T

    k_attn<<<dim3(1024, 12), 256>>>();

    k_mma<<<gg, 256, 65536>>>(2, 3, projw, projb);                // a = att @ Wp^T + b

    k_final<<<RTOT, 256>>>(n2g, n2b, f1w, f1b, f2w, f2b, out);
}

// round 4
// speedup vs baseline: 5.4975x; 4.8630x over previous
#include <cuda_runtime.h>
#include <cuda_fp16.h>
#include <math.h>

#define RTOT 65536
#define CD   768
#define EPS  1e-5f

// ---------------- scratch (static __device__, allocation-free) --------------
__device__ __half g_xh [RTOT*CD];   // LN1 out (windowed order), fp16
__device__ __half g_qinh[RTOT*CD];  // green+blue
__device__ __half g_kinh[RTOT*CD];  // red
__device__ __half g_qh [RTOT*CD];
__device__ __half g_kh [RTOT*CD];
__device__ __half g_vh [RTOT*CD];
__device__ __half g_ath[RTOT*CD];   // attention out
__device__ float  g_a  [RTOT*CD];   // proj out (fp32 for LN2 accuracy)
__device__ __half g_wh [4*589824];  // fp16 weights: Wq,Wk,Wv,Wp

// ---------------- small helpers --------------------------------------------
__device__ __forceinline__ void cp16(void* dst, const void* src) {
    unsigned d = (unsigned)__cvta_generic_to_shared(dst);
    asm volatile("cp.async.cg.shared.global [%0], [%1], 16;\n" :: "r"(d), "l"(src));
}
__device__ __forceinline__ void ldsm4(unsigned &r0, unsigned &r1, unsigned &r2, unsigned &r3, unsigned a) {
    asm volatile("ldmatrix.sync.aligned.m8n8.x4.shared.b16 {%0,%1,%2,%3}, [%4];"
                 : "=r"(r0), "=r"(r1), "=r"(r2), "=r"(r3) : "r"(a));
}
__device__ __forceinline__ void ldsm4t(unsigned &r0, unsigned &r1, unsigned &r2, unsigned &r3, unsigned a) {
    asm volatile("ldmatrix.sync.aligned.m8n8.x4.trans.shared.b16 {%0,%1,%2,%3}, [%4];"
                 : "=r"(r0), "=r"(r1), "=r"(r2), "=r"(r3) : "r"(a));
}
__device__ __forceinline__ void mma16816(float* c, const unsigned* a, const unsigned* b) {
    asm volatile(
        "mma.sync.aligned.m16n8k16.row.col.f32.f16.f16.f32 "
        "{%0,%1,%2,%3}, {%4,%5,%6,%7}, {%8,%9}, {%0,%1,%2,%3};\n"
        : "+f"(c[0]), "+f"(c[1]), "+f"(c[2]), "+f"(c[3])
        : "r"(a[0]), "r"(a[1]), "r"(a[2]), "r"(a[3]), "r"(b[0]), "r"(b[1]));
}
__device__ __forceinline__ unsigned packh2(float x, float y) {
    __half2 h = __floats2half2_rn(x, y);
    return *reinterpret_cast<unsigned*>(&h);
}

// ---------------------------------------------------------------------------
// Kernel 0: weights fp32 -> fp16 (once per launch)
// ---------------------------------------------------------------------------
__global__ void k_w2h(const float* __restrict__ qkv, const float* __restrict__ proj) {
    int i = blockIdx.x * 256 + threadIdx.x;   // grid covers 4*589824 exactly
    float v = (i < 1769472) ? qkv[i] : proj[i - 1769472];
    g_wh[i] = __float2half_rn(v);
}

// ---------------------------------------------------------------------------
// Kernel 1: LN1 fused with window partition -> fp16 windowed rows
// ---------------------------------------------------------------------------
__global__ void k_ln1(const float* __restrict__ x,
                      const float* __restrict__ g,
                      const float* __restrict__ b) {
    int wr  = blockIdx.x;
    int win = wr >> 6, t = wr & 63;
    int bb  = win >> 8, rem = win & 255;
    int wh  = rem >> 4, ww = rem & 15;
    int ii  = t >> 3,  jj = t & 7;
    int sr  = bb * 16384 + (wh * 8 + ii) * 128 + ww * 8 + jj;

    const float* xr = x + (size_t)sr * CD;
    int tid = threadIdx.x;
    float v0 = xr[tid], v1 = xr[tid + 256], v2 = xr[tid + 512];
    float ls = v0 + v1 + v2;
    float lq = v0*v0 + v1*v1 + v2*v2;
    #pragma unroll
    for (int o = 16; o > 0; o >>= 1) {
        ls += __shfl_xor_sync(0xffffffffu, ls, o);
        lq += __shfl_xor_sync(0xffffffffu, lq, o);
    }
    __shared__ float ss[8], sq[8];
    int wid = tid >> 5;
    if ((tid & 31) == 0) { ss[wid] = ls; sq[wid] = lq; }
    __syncthreads();
    float S = 0.f, Q = 0.f;
    #pragma unroll
    for (int k = 0; k < 8; k++) { S += ss[k]; Q += sq[k]; }
    float m   = S * (1.f / 768.f);
    float var = Q * (1.f / 768.f) - m * m;
    float inv = rsqrtf(var + EPS);

    __half* o = g_xh + (size_t)wr * CD;
    o[tid      ] = __float2half_rn((v0 - m) * inv * g[tid      ] + b[tid      ]);
    o[tid + 256] = __float2half_rn((v1 - m) * inv * g[tid + 256] + b[tid + 256]);
    o[tid + 512] = __float2half_rn((v2 - m) * inv * g[tid + 512] + b[tid + 512]);
}

// ---------------------------------------------------------------------------
// Kernel 2: reshape(3,..)/tile shuffle. kin = red, qin = green + blue.
// ---------------------------------------------------------------------------
__global__ void k_gather() {
    int r   = blockIdx.x;
    int tid = threadIdx.x;
    #pragma unroll
    for (int cb = 0; cb < 3; cb++) {
        int rho = (3 * r + cb) & 65535;
        int w0 = rho, w1 = 65536 + rho, w2 = 131072 + rho;
        const __half* s0 = g_xh + (size_t)(w0 / 3) * CD + (w0 % 3) * 256;
        const __half* s1 = g_xh + (size_t)(w1 / 3) * CD + (w1 % 3) * 256;
        const __half* s2 = g_xh + (size_t)(w2 / 3) * CD + (w2 % 3) * 256;
        float red = __half2float(s0[tid]);
        float gb  = __half2float(s1[tid]) + __half2float(s2[tid]);
        size_t o = (size_t)r * CD + cb * 256 + tid;
        g_kinh[o] = __float2half_rn(red);
        g_qinh[o] = __float2half_rn(gb);
    }
}

// ---------------------------------------------------------------------------
// Kernel 3: fp16 tensor GEMM  C[r,n] = sum_k A[r,k]*W[n,k] (+bias)
// 128x128x64 tiles, 256 threads (8 warps 4x2, warp tile 32x64),
// mma.m16n8k16.f16.f32, ldmatrix.x4 fragments, cp.async 2-stage pipeline.
// ---------------------------------------------------------------------------
__device__ __forceinline__ const __half* srcSelH(int s) {
    switch (s) { case 0: return g_qinh; case 1: return g_kinh; default: return g_ath; }
}
__device__ __forceinline__ __half* dstSelH(int s) {
    switch (s) { case 0: return g_qh; case 1: return g_kh; case 2: return g_vh; default: return nullptr; }
}

__global__ __launch_bounds__(256, 2) void k_hgemm(int aSel, int cSel, int wOff,
                                                  const float* __restrict__ bias) {
    extern __shared__ __align__(16) __half smh[];
    const __half* A = srcSelH(aSel);
    const __half* W = g_wh + wOff;
    __half* Ch = dstSelH(cSel);

    int tid  = threadIdx.x;
    int lane = tid & 31, wid = tid >> 5;
    int wm = wid & 3, wn = wid >> 2;
    int m0 = blockIdx.y * 128, n0 = blockIdx.x * 128;
    int g  = lane >> 2, tg = lane & 3;
    int mA = lane >> 3;

    // stage layout (halves): [A0 8192][B0 8192][A1 8192][B1 8192]
    __half* AsP[2] = { smh,          smh + 16384 };
    __half* BsP[2] = { smh + 8192,   smh + 24576 };

    int frow = tid >> 1;
    int gpar = tid & 1;
    const __half* Arow = A + (size_t)(m0 + frow) * CD;
    const __half* Wrow = W + (size_t)(n0 + frow) * CD;

    auto fill = [&](int s, int k0) {
        #pragma unroll
        for (int j = 0; j < 4; j++) {
            int gr = gpar + 2 * j;
            int sw = gr ^ (frow & 7);
            cp16(AsP[s] + frow * 64 + sw * 8, Arow + k0 + gr * 8);
            cp16(BsP[s] + frow * 64 + sw * 8, Wrow + k0 + gr * 8);
        }
    };

    float acc[2][8][4];
    #pragma unroll
    for (int i = 0; i < 2; i++)
        #pragma unroll
        for (int j = 0; j < 8; j++)
            #pragma unroll
            for (int c = 0; c < 4; c++) acc[i][j][c] = 0.f;

    fill(0, 0);
    asm volatile("cp.async.commit_group;\n");

    for (int kt = 0; kt < 12; kt++) {
        if (kt < 11) {
            fill((kt + 1) & 1, (kt + 1) * 64);
            asm volatile("cp.async.commit_group;\n");
            asm volatile("cp.async.wait_group 1;\n");
        } else {
            asm volatile("cp.async.wait_group 0;\n");
        }
        __syncthreads();

        unsigned aBase = (unsigned)__cvta_generic_to_shared(AsP[kt & 1]);
        unsigned bBase = (unsigned)__cvta_generic_to_shared(BsP[kt & 1]);

        #pragma unroll
        for (int kc = 0; kc < 4; kc++) {
            unsigned afr[2][4];
            #pragma unroll
            for (int im = 0; im < 2; im++) {
                int row = wm * 32 + im * 16 + (mA & 1) * 8 + (lane & 7);
                int gr  = kc * 2 + (mA >> 1);
                int sw  = gr ^ (row & 7);
                ldsm4(afr[im][0], afr[im][1], afr[im][2], afr[im][3],
                      aBase + (unsigned)(row * 64 + sw * 8) * 2u);
            }
            unsigned bfr[8][2];
            #pragma unroll
            for (int pr = 0; pr < 4; pr++) {
                int n  = wn * 64 + pr * 16 + ((lane >> 4) * 8) + (lane & 7);
                int kg = kc * 2 + ((lane >> 3) & 1);
                int sw = kg ^ (n & 7);
                unsigned r0, r1, r2, r3;
                ldsm4(r0, r1, r2, r3, bBase + (unsigned)(n * 64 + sw * 8) * 2u);
                bfr[pr*2][0] = r0; bfr[pr*2][1] = r1;
                bfr[pr*2+1][0] = r2; bfr[pr*2+1][1] = r3;
            }
            #pragma unroll
            for (int im = 0; im < 2; im++)
                #pragma unroll
                for (int in_ = 0; in_ < 8; in_++)
                    mma16816(acc[im][in_], afr[im], bfr[in_]);
        }
        __syncthreads();
    }

    // epilogue
    #pragma unroll
    for (int im = 0; im < 2; im++) {
        int row = m0 + wm * 32 + im * 16 + g;
        #pragma unroll
        for (int in_ = 0; in_ < 8; in_++) {
            int col = n0 + wn * 64 + in_ * 8 + 2 * tg;
            float c0 = acc[im][in_][0], c1 = acc[im][in_][1];
            float c2 = acc[im][in_][2], c3 = acc[im][in_][3];
            if (Ch) {
                *reinterpret_cast<unsigned*>(&Ch[(size_t)row * CD + col])       = packh2(c0, c1);
                *reinterpret_cast<unsigned*>(&Ch[(size_t)(row + 8) * CD + col]) = packh2(c2, c3);
            } else {
                float b0 = bias ? bias[col] : 0.f, b1 = bias ? bias[col + 1] : 0.f;
                *(float2*)(g_a + (size_t)row * CD + col)       = make_float2(c0 + b0, c1 + b1);
                *(float2*)(g_a + (size_t)(row + 8) * CD + col) = make_float2(c2 + b0, c3 + b1);
            }
        }
    }
}

// ---------------------------------------------------------------------------
// Kernel 4: attention, one block per (window, head). N=64, D=64.
// Tensor-core: S=QK^T (mma), register softmax, P stays in regs as A-frags,
// O = P @ V with V via ldmatrix.trans. 128 threads (4 warps, 16 rows each).
// ---------------------------------------------------------------------------
__global__ __launch_bounds__(128) void k_attn() {
    __shared__ __half Qs[64 * 72], Ks[64 * 72], Vs[64 * 72];
    int win = blockIdx.x, hd = blockIdx.y;
    int r0 = win * 64, co = hd * 64;
    int tid = threadIdx.x, lane = tid & 31, wid = tid >> 5;
    int g = lane >> 2, tg = lane & 3;
    int mA = lane >> 3;

    // cooperative fill: 64 rows x 8 granules per matrix; 2 threads/row, 4 gran each
    {
        int row = tid >> 1, gp = tid & 1;
        size_t gbase = (size_t)(r0 + row) * CD + co;
        const __half* qs = g_qh + gbase;
        const __half* ks = g_kh + gbase;
        const __half* vs = g_vh + gbase;
        #pragma unroll
        for (int j = 0; j < 4; j++) {
            int gr = gp + 2 * j;
            cp16(Qs + row * 72 + gr * 8, qs + gr * 8);
            cp16(Ks + row * 72 + gr * 8, ks + gr * 8);
            cp16(Vs + row * 72 + gr * 8, vs + gr * 8);
        }
    }
    asm volatile("cp.async.commit_group;\n");
    asm volatile("cp.async.wait_group 0;\n");
    __syncthreads();

    unsigned qB = (unsigned)__cvta_generic_to_shared(Qs);
    unsigned kB = (unsigned)__cvta_generic_to_shared(Ks);
    unsigned vB = (unsigned)__cvta_generic_to_shared(Vs);

    // S = Q K^T   (warp rows: wid*16 .. +15)
    float sc[8][4];
    #pragma unroll
    for (int j = 0; j < 8; j++)
        #pragma unroll
        for (int c = 0; c < 4; c++) sc[j][c] = 0.f;

    #pragma unroll
    for (int kc = 0; kc < 4; kc++) {
        unsigned afr[4];
        {
            int r = wid * 16 + (mA & 1) * 8 + (lane & 7);
            ldsm4(afr[0], afr[1], afr[2], afr[3],
                  qB + (unsigned)(r * 72 + kc * 16 + (mA >> 1) * 8) * 2u);
        }
        unsigned bfr[8][2];
        #pragma unroll
        for (int pr = 0; pr < 4; pr++) {
            int n = pr * 16 + ((lane >> 4) * 8) + (lane & 7);
            unsigned r0_, r1_, r2_, r3_;
            ldsm4(r0_, r1_, r2_, r3_,
                  kB + (unsigned)(n * 72 + kc * 16 + ((lane >> 3) & 1) * 8) * 2u);
            bfr[pr*2][0] = r0_; bfr[pr*2][1] = r1_;
            bfr[pr*2+1][0] = r2_; bfr[pr*2+1][1] = r3_;
        }
        #pragma unroll
        for (int in_ = 0; in_ < 8; in_++)
            mma16816(sc[in_], afr, bfr[in_]);
    }

    // softmax on the two rows this thread owns (rows g and g+8 of warp tile)
    const float scale = 0.125f;
    float m0 = -1e30f, m1 = -1e30f;
    #pragma unroll
    for (int j = 0; j < 8; j++) {
        sc[j][0] *= scale; sc[j][1] *= scale; sc[j][2] *= scale; sc[j][3] *= scale;
        m0 = fmaxf(m0, fmaxf(sc[j][0], sc[j][1]));
        m1 = fmaxf(m1, fmaxf(sc[j][2], sc[j][3]));
    }
    #pragma unroll
    for (int o = 1; o < 4; o <<= 1) {
        m0 = fmaxf(m0, __shfl_xor_sync(0xffffffffu, m0, o));
        m1 = fmaxf(m1, __shfl_xor_sync(0xffffffffu, m1, o));
    }
    float s0 = 0.f, s1 = 0.f;
    #pragma unroll
    for (int j = 0; j < 8; j++) {
        sc[j][0] = __expf(sc[j][0] - m0); sc[j][1] = __expf(sc[j][1] - m0);
        sc[j][2] = __expf(sc[j][2] - m1); sc[j][3] = __expf(sc[j][3] - m1);
        s0 += sc[j][0] + sc[j][1];
        s1 += sc[j][2] + sc[j][3];
    }
    #pragma unroll
    for (int o = 1; o < 4; o <<= 1) {
        s0 += __shfl_xor_sync(0xffffffffu, s0, o);
        s1 += __shfl_xor_sync(0xffffffffu, s1, o);
    }
    float i0 = 1.f / s0, i1 = 1.f / s1;
    unsigned p0[8], p1[8];
    #pragma unroll
    for (int j = 0; j < 8; j++) {
        p0[j] = packh2(sc[j][0] * i0, sc[j][1] * i0);
        p1[j] = packh2(sc[j][2] * i1, sc[j][3] * i1);
    }

    // O = P @ V  (P from registers; V via ldmatrix.trans)
    float oc[8][4];
    #pragma unroll
    for (int j = 0; j < 8; j++)
        #pragma unroll
        for (int c = 0; c < 4; c++) oc[j][c] = 0.f;

    #pragma unroll
    for (int kc = 0; kc < 4; kc++) {
        unsigned afr[4] = { p0[2*kc], p1[2*kc], p0[2*kc+1], p1[2*kc+1] };
        unsigned bfr[8][2];
        #pragma unroll
        for (int pr = 0; pr < 4; pr++) {
            int t = kc * 16 + (lane & 7) + 8 * ((lane >> 3) & 1);
            int n = pr * 16 + 8 * (lane >> 4);
            unsigned r0_, r1_, r2_, r3_;
            ldsm4t(r0_, r1_, r2_, r3_, vB + (unsigned)(t * 72 + n) * 2u);
            bfr[pr*2][0] = r0_; bfr[pr*2][1] = r1_;
            bfr[pr*2+1][0] = r2_; bfr[pr*2+1][1] = r3_;
        }
        #pragma unroll
        for (int in_ = 0; in_ < 8; in_++)
            mma16816(oc[in_], afr, bfr[in_]);
    }

    // write O (fp16, feeds proj GEMM)
    int rowA = r0 + wid * 16 + g;
    #pragma unroll
    for (int in_ = 0; in_ < 8; in_++) {
        int col = co + in_ * 8 + 2 * tg;
        *reinterpret_cast<unsigned*>(&g_ath[(size_t)rowA * CD + col])       = packh2(oc[in_][0], oc[in_][1]);
        *reinterpret_cast<unsigned*>(&g_ath[(size_t)(rowA + 8) * CD + col]) = packh2(oc[in_][2], oc[in_][3]);
    }
}

// ---------------------------------------------------------------------------
// Kernel 5: fused LN2 + MLP (hidden dim 1 -> rank-1 output). fp32 in/out.
// ---------------------------------------------------------------------------
__global__ void k_final(const float* __restrict__ n2g, const float* __restrict__ n2b,
                        const float* __restrict__ f1w, const float* __restrict__ f1b,
                        const float* __restrict__ f2w, const float* __restrict__ f2b,
                        float* __restrict__ out) {
    int r = blockIdx.x;
    const float* a = g_a + (size_t)r * CD;
    int tid = threadIdx.x;
    float s1 = 0.f, s2 = 0.f, s3 = 0.f, s4 = 0.f, s5 = 0.f;
    #pragma unroll
    for (int u = 0; u < 3; u++) {
        int c = tid + 256 * u;
        float x = a[c];
        float wt = n2g[c] * f1w[c];
        s1 += x; s2 += x * x; s3 += x * wt; s4 += wt; s5 += n2b[c] * f1w[c];
    }
    #pragma unroll
    for (int o = 16; o > 0; o >>= 1) {
        s1 += __shfl_xor_sync(0xffffffffu, s1, o);
        s2 += __shfl_xor_sync(0xffffffffu, s2, o);
        s3 += __shfl_xor_sync(0xffffffffu, s3, o);
        s4 += __shfl_xor_sync(0xffffffffu, s4, o);
        s5 += __shfl_xor_sync(0xffffffffu, s5, o);
    }
    __shared__ float sh[8][5];
    int wid = tid >> 5;
    if ((tid & 31) == 0) {
        sh[wid][0]=s1; sh[wid][1]=s2; sh[wid][2]=s3; sh[wid][3]=s4; sh[wid][4]=s5;
    }
    __syncthreads();
    float S1=0.f,S2=0.f,S3=0.f,S4=0.f,S5=0.f;
    #pragma unroll
    for (int k = 0; k < 8; k++) {
        S1+=sh[k][0]; S2+=sh[k][1]; S3+=sh[k][2]; S4+=sh[k][3]; S5+=sh[k][4];
    }
    float m   = S1 * (1.f / 768.f);
    float var = S2 * (1.f / 768.f) - m * m;
    float inv = rsqrtf(var + EPS);
    float s   = (S3 - m * S4) * inv + S5 + f1b[0];
    float hdn = 0.5f * s * (1.f + erff(s * 0.70710678118654752f));

    float* o = out + (size_t)r * CD;
    #pragma unroll
    for (int u = 0; u < 3; u++) {
        int c = tid + 256 * u;
        o[c] = hdn * f2w[c] + f2b[c];
    }
}

// ---------------------------------------------------------------------------
extern "C" void kernel_launch(void* const* d_in, const int* in_sizes, int n_in,
                              void* d_out, int out_size) {
    const float* x     = (const float*)d_in[0];
    const float* n1g   = (const float*)d_in[1];
    const float* n1b   = (const float*)d_in[2];
    const float* n2g   = (const float*)d_in[3];
    const float* n2b   = (const float*)d_in[4];
    const float* qkvw  = (const float*)d_in[5];
    const float* projw = (const float*)d_in[6];
    const float* projb = (const float*)d_in[7];
    const float* f1w   = (const float*)d_in[8];
    const float* f1b   = (const float*)d_in[9];
    const float* f2w   = (const float*)d_in[10];
    const float* f2b   = (const float*)d_in[11];
    float* out = (float*)d_out;

    cudaFuncSetAttribute(k_hgemm, cudaFuncAttributeMaxDynamicSharedMemorySize, 65536);

    k_w2h<<<9216, 256>>>(qkvw, projw);
    k_ln1<<<RTOT, 256>>>(x, n1g, n1b);
    k_gather<<<RTOT, 256>>>();

    dim3 gg(6, 512);
    k_hgemm<<<gg, 256, 65536>>>(0, 0, 0,           nullptr);  // Q
    k_hgemm<<<gg, 256, 65536>>>(1, 1, 589824,      nullptr);  // K
    k_hgemm<<<gg, 256, 65536>>>(1, 2, 2 * 589824,  nullptr);  // V

    k_attn<<<dim3(1024, 12), 128>>>();

    k_hgemm<<<gg, 256, 65536>>>(2, 3, 3 * 589824,  projb);    // proj -> g_a (fp32)

    k_final<<<RTOT, 256>>>(n2g, n2b, f1w, f1b, f2w, f2b, out);
}